// round 6
// baseline (speedup 1.0000x reference)
#include <cuda_runtime.h>
#include <cuda_bf16.h>
#include <cstdint>
#include <cfloat>

#define B_    64
#define H_    512
#define N_    16384
#define W_    64
#define DIN_  512
#define KDIM_ 1088
#define G4_   2048
#define KSPLIT_ 16
#define KPER_   68    // 1088/16

// d_out layout (floats)
#define OFF_Y   0
#define OFF_H   32768
#define OFF_C   65536
#define OFF_M   98304
#define OFF_WR  67207168
#define OFF_US  68255744
#define OFF_R   69304320

// scratch
__device__ float g_zp[KSPLIT_ * B_ * G4_];
__device__ float g_qn[B_ * W_];
__device__ float g_a[B_ * W_];
__device__ float g_e[B_ * W_];
__device__ float g_alpha[B_];
__device__ float g_gamma[B_];
__device__ float g_sim[B_ * N_];
__device__ float g_simv[512 * 4];      // 8 blocks/b * 4 candidates
__device__ int   g_simi[512 * 4];
__device__ float g_usv[512 * 5];       // 8 blocks/b * 5 candidates
__device__ int   g_usi[512 * 5];

__device__ __forceinline__ float sigmoidf_(float x) { return 1.0f / (1.0f + expf(-x)); }

template<int KK>
__device__ __forceinline__ void insert_sorted(float* lv, int* li, float v, int n) {
    if (v > lv[KK-1] || (v == lv[KK-1] && n < li[KK-1])) {
        lv[KK-1] = v; li[KK-1] = n;
#pragma unroll
        for (int p = KK-1; p > 0; p--) {
            bool up = (lv[p] > lv[p-1]) || (lv[p] == lv[p-1] && li[p] < li[p-1]);
            if (up) {
                float tv = lv[p]; lv[p] = lv[p-1]; lv[p-1] = tv;
                int   ti = li[p]; li[p] = li[p-1]; li[p-1] = ti;
            }
        }
    }
}

template<int KK>
__device__ __forceinline__ void merge2(float* v, int* ix, const float* v2, const int* i2) {
    float ov[KK]; int oi[KK]; int pa = 0, pb = 0;
#pragma unroll
    for (int t = 0; t < KK; t++) {
        bool ta;
        if (pa >= KK) ta = false;
        else if (pb >= KK) ta = true;
        else ta = (v[pa] > v2[pb]) || (v[pa] == v2[pb] && ix[pa] < i2[pb]);
        if (ta) { ov[t] = v[pa]; oi[t] = ix[pa]; pa++; }
        else    { ov[t] = v2[pb]; oi[t] = i2[pb]; pb++; }
    }
#pragma unroll
    for (int t = 0; t < KK; t++) { v[t] = ov[t]; ix[t] = oi[t]; }
}

// warp-level merge of sorted KK-lists held in registers; result valid at lane 0
template<int KK>
__device__ __forceinline__ void warp_merge(float* v, int* ix) {
#pragma unroll
    for (int off = 16; off > 0; off >>= 1) {
        float v2[KK]; int i2[KK];
#pragma unroll
        for (int j = 0; j < KK; j++) {
            v2[j] = __shfl_down_sync(0xffffffffu, v[j], off);
            i2[j] = __shfl_down_sync(0xffffffffu, ix[j], off);
        }
        merge2<KK>(v, ix, v2, i2);
    }
}

// ---------------------------------------------------------------------------
// K1: z partials. grid = 32 j-tiles x 16 k-splits = 512 blocks, 256 threads.
// ---------------------------------------------------------------------------
__global__ void k_gemm_z(const float* __restrict__ inp, const float* __restrict__ rprev,
                         const float* __restrict__ hprev, const float* __restrict__ Wk,
                         const float* __restrict__ Uk) {
    __shared__ __align__(16) float Xs[4][64];
    __shared__ __align__(16) float Ws[4][64];
    const int jt = blockIdx.x & 31;
    const int ks = blockIdx.x >> 5;
    const int j0 = jt * 64;
    const int kbase = ks * KPER_;
    const int t = threadIdx.x;
    const int tj = t & 15;
    const int tb = t >> 4;

    float acc[4][4];
#pragma unroll
    for (int r = 0; r < 4; r++)
#pragma unroll
        for (int c = 0; c < 4; c++) acc[r][c] = 0.0f;

    for (int cch = 0; cch < 17; cch++) {
        const int k0 = kbase + cch * 4;
        {
            int b = t >> 2, kk = t & 3, kg = k0 + kk;
            float v;
            if (kg < DIN_)            v = inp[b * DIN_ + kg];
            else if (kg < DIN_ + W_)  v = rprev[b * W_ + (kg - DIN_)];
            else                      v = hprev[b * H_ + (kg - DIN_ - W_)];
            Xs[kk][b] = v;
        }
        {
            int kk = t >> 6, jj = t & 63, kg = k0 + kk;
            float w = (kg < DIN_ + W_) ? Wk[kg * G4_ + j0 + jj]
                                       : Uk[(kg - DIN_ - W_) * G4_ + j0 + jj];
            Ws[kk][jj] = w;
        }
        __syncthreads();
#pragma unroll
        for (int kk = 0; kk < 4; kk++) {
            float4 xv = *(const float4*)&Xs[kk][tb * 4];
            float4 wv = *(const float4*)&Ws[kk][tj * 4];
            float xr[4] = {xv.x, xv.y, xv.z, xv.w};
            float wc[4] = {wv.x, wv.y, wv.z, wv.w};
#pragma unroll
            for (int r = 0; r < 4; r++)
#pragma unroll
                for (int c = 0; c < 4; c++) acc[r][c] += xr[r] * wc[c];
        }
        __syncthreads();
    }
#pragma unroll
    for (int r = 0; r < 4; r++) {
        float4 st = make_float4(acc[r][0], acc[r][1], acc[r][2], acc[r][3]);
        *(float4*)&g_zp[ks * (B_ * G4_) + (tb * 4 + r) * G4_ + j0 + tj * 4] = st;
    }
}

// ---------------------------------------------------------------------------
// K2: z reduce + gates + params + derive. grid=64 (b), block=256
// ---------------------------------------------------------------------------
__global__ void k_hparams(const float* __restrict__ cprev, const float* __restrict__ bl,
                          const float* __restrict__ Wp, const float* __restrict__ bp,
                          float* __restrict__ h_out, float* __restrict__ c_out) {
    __shared__ float zz[G4_];
    __shared__ float sh[H_];
    __shared__ float sp[194];
    __shared__ float ws[2];
    const int b = blockIdx.x, tid = threadIdx.x;

#pragma unroll
    for (int i = 0; i < 8; i++) {
        const int hh = tid + i * 256;
        float z = bl[hh];
#pragma unroll
        for (int ks = 0; ks < KSPLIT_; ks++)
            z += g_zp[ks * (B_ * G4_) + b * G4_ + hh];
        zz[hh] = z;
    }
    __syncthreads();

#pragma unroll
    for (int i = 0; i < 2; i++) {
        const int hh = tid + i * 256;
        float ig = sigmoidf_(zz[hh]);
        float fg = sigmoidf_(zz[H_ + hh]);
        float og = sigmoidf_(zz[3 * H_ + hh]);
        float c  = fg * cprev[b * H_ + hh] + ig * tanhf(zz[2 * H_ + hh]);
        float h  = og * tanhf(c);
        c_out[b * H_ + hh] = c;
        h_out[b * H_ + hh] = h;
        sh[hh] = h;
    }
    __syncthreads();

    if (tid < 194) {
        float acc = bp[tid];
#pragma unroll 4
        for (int k = 0; k < H_; k++) acc += sh[k] * Wp[k * 194 + tid];
        sp[tid] = acc;
    }
    __syncthreads();

    if (tid < 64) {
        float q = sp[tid];
        float s = q * q;
#pragma unroll
        for (int off = 16; off > 0; off >>= 1) s += __shfl_down_sync(0xffffffffu, s, off);
        if ((tid & 31) == 0) ws[tid >> 5] = s;
    }
    __syncthreads();
    if (tid < 64) {
        float tot = ws[0] + ws[1];
        g_qn[b * W_ + tid] = sp[tid] * rsqrtf(fmaxf(tot, 1e-12f));
        g_a[b * W_ + tid]  = sp[W_ + tid];
        g_e[b * W_ + tid]  = sigmoidf_(sp[2 * W_ + tid]);
        if (tid == 0) {
            g_alpha[b] = sigmoidf_(sp[192]);
            g_gamma[b] = sigmoidf_(sp[193]);
        }
    }
}

// ---------------------------------------------------------------------------
// K3 (FUSED): one pass over M: sim + base M update + us/wr streams.
// grid = 8192 blocks (128 rows each), block = 256. NO reductions here.
// ---------------------------------------------------------------------------
__global__ void k_fused(const float* __restrict__ M, const float* __restrict__ wrp,
                        const float* __restrict__ usprev,
                        float* __restrict__ Mout, float* __restrict__ wr_out,
                        float* __restrict__ us_out) {
    const int b  = blockIdx.x >> 7;
    const int n0 = (blockIdx.x & 127) << 7;
    const int tid = threadIdx.x;
    __shared__ __align__(16) float se[W_], sa[W_], sq[W_];
    __shared__ float s_sim[128];
    __shared__ float s_ag;
    if (tid < W_) { se[tid] = g_e[b * W_ + tid]; sa[tid] = g_a[b * W_ + tid]; sq[tid] = g_qn[b * W_ + tid]; }
    if (tid == 0) s_ag = g_alpha[b] * g_gamma[b];
    __syncthreads();

    const int lane = tid & 31, warp = tid >> 5;
    const int half = lane >> 4, l16 = lane & 15;
    const int rbase = warp * 2 + half;
    const size_t browoff = (size_t)b * N_ + n0;

    float4 m[8];
    float wr[8];
#pragma unroll
    for (int i = 0; i < 8; i++)
        m[i] = __ldcs((const float4*)(M + (browoff + i * 16 + rbase) * W_) + l16);
#pragma unroll
    for (int i = 0; i < 8; i++)
        wr[i] = __ldg(wrp + browoff + i * 16 + rbase);

    // usage / wr output streams (pure streaming, no reduction)
    if (tid < 32) {
        float4 up = __ldcs((const float4*)(usprev + browoff) + tid);
        __stcs((float4*)(us_out + browoff) + tid,
               make_float4(up.x + 1.0f, up.y + 1.0f, up.z + 1.0f, up.w + 1.0f));
        __stcs((float4*)(wr_out + browoff) + tid, make_float4(0.f, 0.f, 0.f, 0.f));
    }

    const float4 e4 = *(const float4*)(se + l16 * 4);
    const float4 a4 = *(const float4*)(sa + l16 * 4);
    const float4 q4 = *(const float4*)(sq + l16 * 4);
    const float ag = s_ag;

#pragma unroll
    for (int i = 0; i < 8; i++) {
        float dot = m[i].x * q4.x + m[i].y * q4.y + m[i].z * q4.z + m[i].w * q4.w;
        float ss  = m[i].x * m[i].x + m[i].y * m[i].y + m[i].z * m[i].z + m[i].w * m[i].w;
#pragma unroll
        for (int off = 8; off > 0; off >>= 1) {
            dot += __shfl_down_sync(0xffffffffu, dot, off);
            ss  += __shfl_down_sync(0xffffffffu, ss,  off);
        }
        if (l16 == 0) s_sim[i * 16 + rbase] = dot * rsqrtf(fmaxf(ss, 1e-12f));

        const float ww = ag * wr[i];
        float4 o;
        o.x = m[i].x * (1.0f - ww * e4.x) + ww * a4.x;
        o.y = m[i].y * (1.0f - ww * e4.y) + ww * a4.y;
        o.z = m[i].z * (1.0f - ww * e4.z) + ww * a4.z;
        o.w = m[i].w * (1.0f - ww * e4.w) + ww * a4.w;
        __stcs((float4*)(Mout + (browoff + i * 16 + rbase) * W_) + l16, o);
    }
    __syncthreads();
    if (tid < 128) g_sim[browoff + tid] = s_sim[tid];
}

// ---------------------------------------------------------------------------
// K4 (read-only reductions, warp-shuffle based):
//   blocks [0,512): top-4 of sim per (b, chunk of 2048)
//   blocks [512,1024): top-5 of usage_prev per (b, chunk of 2048)
// block = 256 (8 warps)
// ---------------------------------------------------------------------------
__global__ void k_sel(const float* __restrict__ usprev) {
    const int tid = threadIdx.x;
    const int lane = tid & 31, warp = tid >> 5;

    if (blockIdx.x < 512) {
        const int b = blockIdx.x >> 3, chunk = blockIdx.x & 7;
        const float* simb = g_sim + b * N_ + chunk * 2048;
        const int nbase = chunk * 2048;
        float lv[4]; int li[4];
#pragma unroll
        for (int j = 0; j < 4; j++) { lv[j] = -FLT_MAX; li[j] = 0x7FFFFFFF; }
        // two float4 loads per thread
        float4 v0 = *((const float4*)simb + tid);
        float4 v1 = *((const float4*)simb + 256 + tid);
        insert_sorted<4>(lv, li, v0.x, nbase + tid * 4 + 0);
        insert_sorted<4>(lv, li, v0.y, nbase + tid * 4 + 1);
        insert_sorted<4>(lv, li, v0.z, nbase + tid * 4 + 2);
        insert_sorted<4>(lv, li, v0.w, nbase + tid * 4 + 3);
        insert_sorted<4>(lv, li, v1.x, nbase + 1024 + tid * 4 + 0);
        insert_sorted<4>(lv, li, v1.y, nbase + 1024 + tid * 4 + 1);
        insert_sorted<4>(lv, li, v1.z, nbase + 1024 + tid * 4 + 2);
        insert_sorted<4>(lv, li, v1.w, nbase + 1024 + tid * 4 + 3);
        warp_merge<4>(lv, li);

        __shared__ float wv[8][4];
        __shared__ int   wi[8][4];
        if (lane == 0) {
#pragma unroll
            for (int j = 0; j < 4; j++) { wv[warp][j] = lv[j]; wi[warp][j] = li[j]; }
        }
        __syncthreads();
        if (warp == 0 && lane < 8) {
#pragma unroll
            for (int j = 0; j < 4; j++) { lv[j] = wv[lane][j]; li[j] = wi[lane][j]; }
#pragma unroll
            for (int off = 4; off > 0; off >>= 1) {
                float v2[4]; int i2[4];
#pragma unroll
                for (int j = 0; j < 4; j++) {
                    v2[j] = __shfl_down_sync(0xffu, lv[j], off);
                    i2[j] = __shfl_down_sync(0xffu, li[j], off);
                }
                merge2<4>(lv, li, v2, i2);
            }
            if (lane == 0) {
#pragma unroll
                for (int j = 0; j < 4; j++) {
                    g_simv[blockIdx.x * 4 + j] = lv[j];
                    g_simi[blockIdx.x * 4 + j] = li[j];
                }
            }
        }
    } else {
        const int blk = blockIdx.x - 512;
        const int b = blk >> 3, chunk = blk & 7;
        const float* usb = usprev + b * N_ + chunk * 2048;
        const int nbase = chunk * 2048;
        float lv[5]; int li[5];
#pragma unroll
        for (int j = 0; j < 5; j++) { lv[j] = -FLT_MAX; li[j] = 0x7FFFFFFF; }
        float4 v0 = __ldcs((const float4*)usb + tid);
        float4 v1 = __ldcs((const float4*)usb + 256 + tid);
        insert_sorted<5>(lv, li, v0.x, nbase + tid * 4 + 0);
        insert_sorted<5>(lv, li, v0.y, nbase + tid * 4 + 1);
        insert_sorted<5>(lv, li, v0.z, nbase + tid * 4 + 2);
        insert_sorted<5>(lv, li, v0.w, nbase + tid * 4 + 3);
        insert_sorted<5>(lv, li, v1.x, nbase + 1024 + tid * 4 + 0);
        insert_sorted<5>(lv, li, v1.y, nbase + 1024 + tid * 4 + 1);
        insert_sorted<5>(lv, li, v1.z, nbase + 1024 + tid * 4 + 2);
        insert_sorted<5>(lv, li, v1.w, nbase + 1024 + tid * 4 + 3);
        warp_merge<5>(lv, li);

        __shared__ float wv[8][5];
        __shared__ int   wi[8][5];
        if (lane == 0) {
#pragma unroll
            for (int j = 0; j < 5; j++) { wv[warp][j] = lv[j]; wi[warp][j] = li[j]; }
        }
        __syncthreads();
        if (warp == 0 && lane < 8) {
#pragma unroll
            for (int j = 0; j < 5; j++) { lv[j] = wv[lane][j]; li[j] = wi[lane][j]; }
#pragma unroll
            for (int off = 4; off > 0; off >>= 1) {
                float v2[5]; int i2[5];
#pragma unroll
                for (int j = 0; j < 5; j++) {
                    v2[j] = __shfl_down_sync(0xffu, lv[j], off);
                    i2[j] = __shfl_down_sync(0xffu, li[j], off);
                }
                merge2<5>(lv, li, v2, i2);
            }
            if (lane == 0) {
#pragma unroll
                for (int j = 0; j < 5; j++) {
                    g_usv[blk * 5 + j] = lv[j];
                    g_usi[blk * 5 + j] = li[j];
                }
            }
        }
    }
}

// ---------------------------------------------------------------------------
// K5 (final): warp-parallel candidate merges; softmax; lru; r_curr;
// lru row fix; wr/us fixups; y_out. grid=64, block=512.
// ---------------------------------------------------------------------------
__global__ void k_final(const float* __restrict__ Mprev, const float* __restrict__ wrp,
                        const float* __restrict__ h, const float* __restrict__ Wf,
                        const float* __restrict__ bf,
                        float* __restrict__ Mout, float* __restrict__ wr_out,
                        float* __restrict__ us_out, float* __restrict__ r_out,
                        float* __restrict__ y) {
    const int b = blockIdx.x, tid = threadIdx.x;
    const int lane = tid & 31, warp = tid >> 5;
    __shared__ float xs[H_];
    __shared__ float s_r[W_];
    __shared__ float s_p[4];
    __shared__ int   s_idx[4];
    __shared__ float s_uv[5];
    __shared__ int   s_ui[5];
    __shared__ int   s_lru;

    xs[tid] = h[b * H_ + tid];

    if (warp == 0) {
        // 32 sim candidates: one per lane
        float lv[4]; int li[4];
        lv[0] = g_simv[b * 32 + lane]; li[0] = g_simi[b * 32 + lane];
#pragma unroll
        for (int j = 1; j < 4; j++) { lv[j] = -FLT_MAX; li[j] = 0x7FFFFFFF; }
        warp_merge<4>(lv, li);
        if (lane == 0) {
            float vmax = lv[0], sum = 0.0f, ev[4];
#pragma unroll
            for (int j = 0; j < 4; j++) { ev[j] = expf(lv[j] - vmax); sum += ev[j]; }
            float inv = 1.0f / sum;
#pragma unroll
            for (int j = 0; j < 4; j++) { s_p[j] = ev[j] * inv; s_idx[j] = li[j]; }
        }
    } else if (warp == 1) {
        // 40 usage candidates (8 blocks * 5): lanes 0..39 -> 2 per lane max
        float lv[5]; int li[5];
#pragma unroll
        for (int j = 0; j < 5; j++) { lv[j] = -FLT_MAX; li[j] = 0x7FFFFFFF; }
        insert_sorted<5>(lv, li, g_usv[b * 40 + lane], g_usi[b * 40 + lane]);
        if (lane < 8)
            insert_sorted<5>(lv, li, g_usv[b * 40 + 32 + lane], g_usi[b * 40 + 32 + lane]);
        warp_merge<5>(lv, li);
        if (lane == 0) {
#pragma unroll
            for (int j = 0; j < 5; j++) { s_uv[j] = lv[j]; s_ui[j] = li[j]; }
        }
    }
    __syncthreads();

    if (tid == 0) {
        int lru = s_ui[0];
#pragma unroll
        for (int j = 0; j < 5; j++) {
            int c = s_ui[j];
            if (c != s_idx[0] && c != s_idx[1] && c != s_idx[2] && c != s_idx[3]) { lru = c; break; }
        }
        s_lru = lru;
    }
    if (tid >= 128 && tid < 192) {
        const int w = tid - 128;
        float r = s_p[0] * Mprev[((size_t)b * N_ + s_idx[0]) * W_ + w]
                + s_p[1] * Mprev[((size_t)b * N_ + s_idx[1]) * W_ + w]
                + s_p[2] * Mprev[((size_t)b * N_ + s_idx[2]) * W_ + w]
                + s_p[3] * Mprev[((size_t)b * N_ + s_idx[3]) * W_ + w];
        s_r[w] = r;
        r_out[b * W_ + w] = r;
    }
    if (tid >= 224 && tid < 228) {
        const int j = tid - 224;
        const int idx = s_idx[j];
        wr_out[b * N_ + idx] = s_p[j];
        us_out[b * N_ + idx] = 0.0f;
    }
    __syncthreads();

    if (tid >= 64 && tid < 80) {
        const int k = tid - 64;
        const int lru = s_lru;
        const float alpha = g_alpha[b], gamma = g_gamma[b];
        const float ww = alpha * (gamma * wrp[b * N_ + lru] + (1.0f - gamma));
        const size_t rowoff = ((size_t)b * N_ + lru) * W_;
        float4 mrow = *(const float4*)(Mprev + rowoff + k * 4);
        float4 e4 = *(const float4*)(g_e + b * W_ + k * 4);
        float4 a4 = *(const float4*)(g_a + b * W_ + k * 4);
        float4 o;
        o.x = mrow.x * (1.0f - ww * e4.x) + ww * a4.x;
        o.y = mrow.y * (1.0f - ww * e4.y) + ww * a4.y;
        o.z = mrow.z * (1.0f - ww * e4.z) + ww * a4.z;
        o.w = mrow.w * (1.0f - ww * e4.w) + ww * a4.w;
        *(float4*)(Mout + rowoff + k * 4) = o;
    }

    float acc = bf[tid];
#pragma unroll 8
    for (int k = 0; k < H_; k++) acc += xs[k] * __ldg(Wf + k * H_ + tid);
#pragma unroll 8
    for (int k = 0; k < W_; k++) acc += s_r[k] * __ldg(Wf + (H_ + k) * H_ + tid);
    y[b * H_ + tid] = acc;
}

// ---------------------------------------------------------------------------
extern "C" void kernel_launch(void* const* d_in, const int* in_sizes, int n_in,
                              void* d_out, int out_size) {
    const float* inputs = (const float*)d_in[0];
    const float* h_prev = (const float*)d_in[1];
    const float* c_prev = (const float*)d_in[2];
    const float* M_prev = (const float*)d_in[3];
    const float* wr_prev = (const float*)d_in[4];
    const float* usage_prev = (const float*)d_in[5];
    const float* r_prev = (const float*)d_in[6];
    const float* Wk = (const float*)d_in[7];
    const float* Uk = (const float*)d_in[8];
    const float* b_lstm = (const float*)d_in[9];
    const float* Wp = (const float*)d_in[10];
    const float* bp = (const float*)d_in[11];
    const float* Wf = (const float*)d_in[12];
    const float* bf = (const float*)d_in[13];

    float* out = (float*)d_out;
    float* o_y  = out + OFF_Y;
    float* o_h  = out + OFF_H;
    float* o_c  = out + OFF_C;
    float* o_M  = out + OFF_M;
    float* o_wr = out + OFF_WR;
    float* o_us = out + OFF_US;
    float* o_r  = out + OFF_R;

    k_gemm_z<<<512, 256>>>(inputs, r_prev, h_prev, Wk, Uk);
    k_hparams<<<64, 256>>>(c_prev, b_lstm, Wp, bp, o_h, o_c);
    k_fused<<<8192, 256>>>(M_prev, wr_prev, usage_prev, o_M, o_wr, o_us);
    k_sel<<<1024, 256>>>(usage_prev);
    k_final<<<64, 512>>>(M_prev, wr_prev, o_h, Wf, bf, o_M, o_wr, o_us, o_r, o_y);
}

// round 7
// speedup vs baseline: 1.2127x; 1.2127x over previous
#include <cuda_runtime.h>
#include <cuda_bf16.h>
#include <cstdint>
#include <cfloat>

#define B_    64
#define H_    512
#define N_    16384
#define W_    64
#define DIN_  512
#define KDIM_ 1088
#define G4_   2048
#define KSPLIT_ 16
#define KPER_   68    // 1088/16

// d_out layout (floats)
#define OFF_Y   0
#define OFF_H   32768
#define OFF_C   65536
#define OFF_M   98304
#define OFF_WR  67207168
#define OFF_US  68255744
#define OFF_R   69304320

typedef unsigned long long u64;

// scratch
__device__ float g_zp[KSPLIT_ * B_ * G4_];
__device__ float g_qn[B_ * W_];
__device__ float g_a[B_ * W_];
__device__ float g_e[B_ * W_];
__device__ float g_alpha[B_];
__device__ float g_gamma[B_];
__device__ float g_sim[B_ * N_];
__device__ u64   g_simk[512 * 4];   // 8 blocks/b * top-4 keys
__device__ u64   g_usk[512 * 8];    // 8 blocks/b * top-8 keys

__device__ __forceinline__ float sigmoidf_(float x) { return 1.0f / (1.0f + expf(-x)); }

// ---- packed-key top-k primitives (constant-index CE networks only) ----
__device__ __forceinline__ u64 umax64(u64 a, u64 b) { return a > b ? a : b; }
__device__ __forceinline__ u64 umin64(u64 a, u64 b) { return a < b ? a : b; }
#define CE_DESC(x, y) { u64 _mx = umax64(x, y); u64 _mn = umin64(x, y); (x) = _mx; (y) = _mn; }

__device__ __forceinline__ u64 pack_key(float v, int n) {
    unsigned vb = __float_as_uint(v);
    vb = (vb & 0x80000000u) ? ~vb : (vb | 0x80000000u);
    return ((u64)vb << 32) | (unsigned)(0xFFFFFFFFu - (unsigned)n);
}
__device__ __forceinline__ float key_val(u64 k) {
    unsigned vb = (unsigned)(k >> 32);
    vb = (vb & 0x80000000u) ? (vb ^ 0x80000000u) : ~vb;
    return __uint_as_float(vb);
}
__device__ __forceinline__ int key_idx(u64 k) {
    return (int)(0xFFFFFFFFu - (unsigned)(k & 0xFFFFFFFFull));
}

// insert into sorted-desc 4-list (constant indices)
__device__ __forceinline__ void insert4(u64* a, u64 x) {
    if (x > a[3]) {
        a[3] = x;
        if (a[3] > a[2]) { u64 t = a[2]; a[2] = a[3]; a[3] = t; }
        if (a[2] > a[1]) { u64 t = a[1]; a[1] = a[2]; a[2] = t; }
        if (a[1] > a[0]) { u64 t = a[0]; a[0] = a[1]; a[1] = t; }
    }
}

// bitonic top-4 merge: a (sorted desc) with brev (b reversed) -> a = top4 sorted desc
__device__ __forceinline__ void bmerge4(u64* a, const u64* brev) {
    a[0] = umax64(a[0], brev[0]); a[1] = umax64(a[1], brev[1]);
    a[2] = umax64(a[2], brev[2]); a[3] = umax64(a[3], brev[3]);
    CE_DESC(a[0], a[2]); CE_DESC(a[1], a[3]);
    CE_DESC(a[0], a[1]); CE_DESC(a[2], a[3]);
}

// bitonic top-8 merge
__device__ __forceinline__ void bmerge8(u64* a, const u64* brev) {
#pragma unroll
    for (int j = 0; j < 8; j++) a[j] = umax64(a[j], brev[j]);
    CE_DESC(a[0], a[4]); CE_DESC(a[1], a[5]); CE_DESC(a[2], a[6]); CE_DESC(a[3], a[7]);
    CE_DESC(a[0], a[2]); CE_DESC(a[1], a[3]); CE_DESC(a[4], a[6]); CE_DESC(a[5], a[7]);
    CE_DESC(a[0], a[1]); CE_DESC(a[2], a[3]); CE_DESC(a[4], a[5]); CE_DESC(a[6], a[7]);
}

// insertion-sort network for 8 elements (28 CEs, constant indices)
__device__ __forceinline__ void sort8(u64* a) {
#pragma unroll
    for (int i = 1; i < 8; i++)
#pragma unroll
        for (int j = i; j > 0; j--)
            CE_DESC(a[j-1], a[j]);
}

template<int MAXOFF>
__device__ __forceinline__ void warp_bmerge4(u64* a, unsigned mask) {
#pragma unroll
    for (int off = MAXOFF; off > 0; off >>= 1) {
        u64 b[4];
#pragma unroll
        for (int j = 0; j < 4; j++) b[j] = __shfl_down_sync(mask, a[3-j], off);
        bmerge4(a, b);
    }
}

template<int MAXOFF>
__device__ __forceinline__ void warp_bmerge8(u64* a, unsigned mask) {
#pragma unroll
    for (int off = MAXOFF; off > 0; off >>= 1) {
        u64 b[8];
#pragma unroll
        for (int j = 0; j < 8; j++) b[j] = __shfl_down_sync(mask, a[7-j], off);
        bmerge8(a, b);
    }
}

// ---------------------------------------------------------------------------
// K1: z partials. grid = 32 j-tiles x 16 k-splits = 512 blocks, 256 threads.
// ---------------------------------------------------------------------------
__global__ void k_gemm_z(const float* __restrict__ inp, const float* __restrict__ rprev,
                         const float* __restrict__ hprev, const float* __restrict__ Wk,
                         const float* __restrict__ Uk) {
    __shared__ __align__(16) float Xs[4][64];
    __shared__ __align__(16) float Ws[4][64];
    const int jt = blockIdx.x & 31;
    const int ks = blockIdx.x >> 5;
    const int j0 = jt * 64;
    const int kbase = ks * KPER_;
    const int t = threadIdx.x;
    const int tj = t & 15;
    const int tb = t >> 4;

    float acc[4][4];
#pragma unroll
    for (int r = 0; r < 4; r++)
#pragma unroll
        for (int c = 0; c < 4; c++) acc[r][c] = 0.0f;

    for (int cch = 0; cch < 17; cch++) {
        const int k0 = kbase + cch * 4;
        {
            int b = t >> 2, kk = t & 3, kg = k0 + kk;
            float v;
            if (kg < DIN_)            v = inp[b * DIN_ + kg];
            else if (kg < DIN_ + W_)  v = rprev[b * W_ + (kg - DIN_)];
            else                      v = hprev[b * H_ + (kg - DIN_ - W_)];
            Xs[kk][b] = v;
        }
        {
            int kk = t >> 6, jj = t & 63, kg = k0 + kk;
            float w = (kg < DIN_ + W_) ? Wk[kg * G4_ + j0 + jj]
                                       : Uk[(kg - DIN_ - W_) * G4_ + j0 + jj];
            Ws[kk][jj] = w;
        }
        __syncthreads();
#pragma unroll
        for (int kk = 0; kk < 4; kk++) {
            float4 xv = *(const float4*)&Xs[kk][tb * 4];
            float4 wv = *(const float4*)&Ws[kk][tj * 4];
            float xr[4] = {xv.x, xv.y, xv.z, xv.w};
            float wc[4] = {wv.x, wv.y, wv.z, wv.w};
#pragma unroll
            for (int r = 0; r < 4; r++)
#pragma unroll
                for (int c = 0; c < 4; c++) acc[r][c] += xr[r] * wc[c];
        }
        __syncthreads();
    }
#pragma unroll
    for (int r = 0; r < 4; r++) {
        float4 st = make_float4(acc[r][0], acc[r][1], acc[r][2], acc[r][3]);
        *(float4*)&g_zp[ks * (B_ * G4_) + (tb * 4 + r) * G4_ + j0 + tj * 4] = st;
    }
}

// ---------------------------------------------------------------------------
// K2: z reduce + gates + params + derive. grid=64 (b), block=256
// ---------------------------------------------------------------------------
__global__ void k_hparams(const float* __restrict__ cprev, const float* __restrict__ bl,
                          const float* __restrict__ Wp, const float* __restrict__ bp,
                          float* __restrict__ h_out, float* __restrict__ c_out) {
    __shared__ float zz[G4_];
    __shared__ float sh[H_];
    __shared__ float sp[194];
    __shared__ float ws[2];
    const int b = blockIdx.x, tid = threadIdx.x;

#pragma unroll
    for (int i = 0; i < 8; i++) {
        const int hh = tid + i * 256;
        float z = bl[hh];
#pragma unroll
        for (int ks = 0; ks < KSPLIT_; ks++)
            z += g_zp[ks * (B_ * G4_) + b * G4_ + hh];
        zz[hh] = z;
    }
    __syncthreads();

#pragma unroll
    for (int i = 0; i < 2; i++) {
        const int hh = tid + i * 256;
        float ig = sigmoidf_(zz[hh]);
        float fg = sigmoidf_(zz[H_ + hh]);
        float og = sigmoidf_(zz[3 * H_ + hh]);
        float c  = fg * cprev[b * H_ + hh] + ig * tanhf(zz[2 * H_ + hh]);
        float h  = og * tanhf(c);
        c_out[b * H_ + hh] = c;
        h_out[b * H_ + hh] = h;
        sh[hh] = h;
    }
    __syncthreads();

    if (tid < 194) {
        float acc = bp[tid];
#pragma unroll 4
        for (int k = 0; k < H_; k++) acc += sh[k] * Wp[k * 194 + tid];
        sp[tid] = acc;
    }
    __syncthreads();

    if (tid < 64) {
        float q = sp[tid];
        float s = q * q;
#pragma unroll
        for (int off = 16; off > 0; off >>= 1) s += __shfl_down_sync(0xffffffffu, s, off);
        if ((tid & 31) == 0) ws[tid >> 5] = s;
    }
    __syncthreads();
    if (tid < 64) {
        float tot = ws[0] + ws[1];
        g_qn[b * W_ + tid] = sp[tid] * rsqrtf(fmaxf(tot, 1e-12f));
        g_a[b * W_ + tid]  = sp[W_ + tid];
        g_e[b * W_ + tid]  = sigmoidf_(sp[2 * W_ + tid]);
        if (tid == 0) {
            g_alpha[b] = sigmoidf_(sp[192]);
            g_gamma[b] = sigmoidf_(sp[193]);
        }
    }
}

// ---------------------------------------------------------------------------
// K3 (FUSED): one pass over M: sim + base M update + us/wr streams.
// grid = 8192 blocks (128 rows each), block = 256.
// ---------------------------------------------------------------------------
__global__ void k_fused(const float* __restrict__ M, const float* __restrict__ wrp,
                        const float* __restrict__ usprev,
                        float* __restrict__ Mout, float* __restrict__ wr_out,
                        float* __restrict__ us_out) {
    const int b  = blockIdx.x >> 7;
    const int n0 = (blockIdx.x & 127) << 7;
    const int tid = threadIdx.x;
    __shared__ __align__(16) float se[W_], sa[W_], sq[W_];
    __shared__ float s_sim[128];
    __shared__ float s_ag;
    if (tid < W_) { se[tid] = g_e[b * W_ + tid]; sa[tid] = g_a[b * W_ + tid]; sq[tid] = g_qn[b * W_ + tid]; }
    if (tid == 0) s_ag = g_alpha[b] * g_gamma[b];
    __syncthreads();

    const int lane = tid & 31, warp = tid >> 5;
    const int half = lane >> 4, l16 = lane & 15;
    const int rbase = warp * 2 + half;
    const size_t browoff = (size_t)b * N_ + n0;

    float4 m[8];
    float wr[8];
#pragma unroll
    for (int i = 0; i < 8; i++)
        m[i] = __ldcs((const float4*)(M + (browoff + i * 16 + rbase) * W_) + l16);
#pragma unroll
    for (int i = 0; i < 8; i++)
        wr[i] = __ldg(wrp + browoff + i * 16 + rbase);

    if (tid < 32) {
        float4 up = __ldcs((const float4*)(usprev + browoff) + tid);
        __stcs((float4*)(us_out + browoff) + tid,
               make_float4(up.x + 1.0f, up.y + 1.0f, up.z + 1.0f, up.w + 1.0f));
        __stcs((float4*)(wr_out + browoff) + tid, make_float4(0.f, 0.f, 0.f, 0.f));
    }

    const float4 e4 = *(const float4*)(se + l16 * 4);
    const float4 a4 = *(const float4*)(sa + l16 * 4);
    const float4 q4 = *(const float4*)(sq + l16 * 4);
    const float ag = s_ag;

#pragma unroll
    for (int i = 0; i < 8; i++) {
        float dot = m[i].x * q4.x + m[i].y * q4.y + m[i].z * q4.z + m[i].w * q4.w;
        float ss  = m[i].x * m[i].x + m[i].y * m[i].y + m[i].z * m[i].z + m[i].w * m[i].w;
#pragma unroll
        for (int off = 8; off > 0; off >>= 1) {
            dot += __shfl_down_sync(0xffffffffu, dot, off);
            ss  += __shfl_down_sync(0xffffffffu, ss,  off);
        }
        if (l16 == 0) s_sim[i * 16 + rbase] = dot * rsqrtf(fmaxf(ss, 1e-12f));

        const float ww = ag * wr[i];
        float4 o;
        o.x = m[i].x * (1.0f - ww * e4.x) + ww * a4.x;
        o.y = m[i].y * (1.0f - ww * e4.y) + ww * a4.y;
        o.z = m[i].z * (1.0f - ww * e4.z) + ww * a4.z;
        o.w = m[i].w * (1.0f - ww * e4.w) + ww * a4.w;
        __stcs((float4*)(Mout + (browoff + i * 16 + rbase) * W_) + l16, o);
    }
    __syncthreads();
    if (tid < 128) g_sim[browoff + tid] = s_sim[tid];
}

// ---------------------------------------------------------------------------
// K4: packed-key reductions.
//   blocks [0,512): top-4 keys of sim per (b, chunk of 2048)
//   blocks [512,1024): top-8 keys of usage_prev per (b, chunk of 2048)
// block = 256 (8 warps)
// ---------------------------------------------------------------------------
__global__ void k_sel(const float* __restrict__ usprev) {
    const int tid = threadIdx.x;
    const int lane = tid & 31, warp = tid >> 5;

    if (blockIdx.x < 512) {
        const int b = blockIdx.x >> 3, chunk = blockIdx.x & 7;
        const float* simb = g_sim + b * N_ + chunk * 2048;
        const int nbase = chunk * 2048;
        u64 a[4] = {0ull, 0ull, 0ull, 0ull};
        float4 v0 = *((const float4*)simb + tid);
        float4 v1 = *((const float4*)simb + 256 + tid);
        insert4(a, pack_key(v0.x, nbase + tid * 4 + 0));
        insert4(a, pack_key(v0.y, nbase + tid * 4 + 1));
        insert4(a, pack_key(v0.z, nbase + tid * 4 + 2));
        insert4(a, pack_key(v0.w, nbase + tid * 4 + 3));
        insert4(a, pack_key(v1.x, nbase + 1024 + tid * 4 + 0));
        insert4(a, pack_key(v1.y, nbase + 1024 + tid * 4 + 1));
        insert4(a, pack_key(v1.z, nbase + 1024 + tid * 4 + 2));
        insert4(a, pack_key(v1.w, nbase + 1024 + tid * 4 + 3));
        warp_bmerge4<16>(a, 0xffffffffu);

        __shared__ u64 sw[8][4];
        if (lane == 0) {
#pragma unroll
            for (int j = 0; j < 4; j++) sw[warp][j] = a[j];
        }
        __syncthreads();
        if (warp == 0 && lane < 8) {
#pragma unroll
            for (int j = 0; j < 4; j++) a[j] = sw[lane][j];
            warp_bmerge4<4>(a, 0xffu);
            if (lane == 0) {
#pragma unroll
                for (int j = 0; j < 4; j++) g_simk[blockIdx.x * 4 + j] = a[j];
            }
        }
    } else {
        const int blk = blockIdx.x - 512;
        const int b = blk >> 3, chunk = blk & 7;
        const float* usb = usprev + b * N_ + chunk * 2048;
        const int nbase = chunk * 2048;
        float4 v0 = __ldcs((const float4*)usb + tid);
        float4 v1 = __ldcs((const float4*)usb + 256 + tid);
        u64 a[8];
        a[0] = pack_key(v0.x, nbase + tid * 4 + 0);
        a[1] = pack_key(v0.y, nbase + tid * 4 + 1);
        a[2] = pack_key(v0.z, nbase + tid * 4 + 2);
        a[3] = pack_key(v0.w, nbase + tid * 4 + 3);
        a[4] = pack_key(v1.x, nbase + 1024 + tid * 4 + 0);
        a[5] = pack_key(v1.y, nbase + 1024 + tid * 4 + 1);
        a[6] = pack_key(v1.z, nbase + 1024 + tid * 4 + 2);
        a[7] = pack_key(v1.w, nbase + 1024 + tid * 4 + 3);
        sort8(a);
        warp_bmerge8<16>(a, 0xffffffffu);

        __shared__ u64 sw8[8][8];
        if (lane == 0) {
#pragma unroll
            for (int j = 0; j < 8; j++) sw8[warp][j] = a[j];
        }
        __syncthreads();
        if (warp == 0 && lane < 8) {
#pragma unroll
            for (int j = 0; j < 8; j++) a[j] = sw8[lane][j];
            warp_bmerge8<4>(a, 0xffu);
            if (lane == 0) {
#pragma unroll
                for (int j = 0; j < 8; j++) g_usk[blk * 8 + j] = a[j];
            }
        }
    }
}

// ---------------------------------------------------------------------------
// K5 (final): bitonic candidate merges; softmax; lru; r_curr; lru row fix;
// wr/us fixups; y_out. grid=64, block=512.
// ---------------------------------------------------------------------------
__global__ void k_final(const float* __restrict__ Mprev, const float* __restrict__ wrp,
                        const float* __restrict__ h, const float* __restrict__ Wf,
                        const float* __restrict__ bf,
                        float* __restrict__ Mout, float* __restrict__ wr_out,
                        float* __restrict__ us_out, float* __restrict__ r_out,
                        float* __restrict__ y) {
    const int b = blockIdx.x, tid = threadIdx.x;
    const int lane = tid & 31, warp = tid >> 5;
    __shared__ float xs[H_];
    __shared__ float s_r[W_];
    __shared__ float s_p[4];
    __shared__ int   s_idx[4];
    __shared__ u64   s_uk[8];
    __shared__ int   s_lru;

    xs[tid] = h[b * H_ + tid];

    if (warp == 0) {
        // 32 sim candidate keys, one per lane
        u64 a[4] = {g_simk[b * 32 + lane], 0ull, 0ull, 0ull};
        warp_bmerge4<16>(a, 0xffffffffu);
        if (lane == 0) {
            float lv[4];
#pragma unroll
            for (int j = 0; j < 4; j++) lv[j] = key_val(a[j]);
            float vmax = lv[0], sum = 0.0f, ev[4];
#pragma unroll
            for (int j = 0; j < 4; j++) { ev[j] = expf(lv[j] - vmax); sum += ev[j]; }
            float inv = 1.0f / sum;
#pragma unroll
            for (int j = 0; j < 4; j++) { s_p[j] = ev[j] * inv; s_idx[j] = key_idx(a[j]); }
        }
    } else if (warp == 1) {
        // 64 usage candidate keys, two per lane (adjacent pair is sorted desc)
        u64 a[8];
        a[0] = g_usk[b * 64 + lane * 2];
        a[1] = g_usk[b * 64 + lane * 2 + 1];
#pragma unroll
        for (int j = 2; j < 8; j++) a[j] = 0ull;
        warp_bmerge8<16>(a, 0xffffffffu);
        if (lane == 0) {
#pragma unroll
            for (int j = 0; j < 8; j++) s_uk[j] = a[j];
        }
    }
    __syncthreads();

    if (tid == 0) {
        int lru = key_idx(s_uk[0]);
#pragma unroll
        for (int j = 0; j < 8; j++) {
            int c = key_idx(s_uk[j]);
            if (c != s_idx[0] && c != s_idx[1] && c != s_idx[2] && c != s_idx[3]) { lru = c; break; }
        }
        s_lru = lru;
    }
    if (tid >= 128 && tid < 192) {
        const int w = tid - 128;
        float r = s_p[0] * Mprev[((size_t)b * N_ + s_idx[0]) * W_ + w]
                + s_p[1] * Mprev[((size_t)b * N_ + s_idx[1]) * W_ + w]
                + s_p[2] * Mprev[((size_t)b * N_ + s_idx[2]) * W_ + w]
                + s_p[3] * Mprev[((size_t)b * N_ + s_idx[3]) * W_ + w];
        s_r[w] = r;
        r_out[b * W_ + w] = r;
    }
    if (tid >= 224 && tid < 228) {
        const int j = tid - 224;
        const int idx = s_idx[j];
        wr_out[b * N_ + idx] = s_p[j];
        us_out[b * N_ + idx] = 0.0f;
    }
    __syncthreads();

    if (tid >= 64 && tid < 80) {
        const int k = tid - 64;
        const int lru = s_lru;
        const float alpha = g_alpha[b], gamma = g_gamma[b];
        const float ww = alpha * (gamma * wrp[b * N_ + lru] + (1.0f - gamma));
        const size_t rowoff = ((size_t)b * N_ + lru) * W_;
        float4 mrow = *(const float4*)(Mprev + rowoff + k * 4);
        float4 e4 = *(const float4*)(g_e + b * W_ + k * 4);
        float4 a4 = *(const float4*)(g_a + b * W_ + k * 4);
        float4 o;
        o.x = mrow.x * (1.0f - ww * e4.x) + ww * a4.x;
        o.y = mrow.y * (1.0f - ww * e4.y) + ww * a4.y;
        o.z = mrow.z * (1.0f - ww * e4.z) + ww * a4.z;
        o.w = mrow.w * (1.0f - ww * e4.w) + ww * a4.w;
        *(float4*)(Mout + rowoff + k * 4) = o;
    }

    float acc = bf[tid];
#pragma unroll 8
    for (int k = 0; k < H_; k++) acc += xs[k] * __ldg(Wf + k * H_ + tid);
#pragma unroll 8
    for (int k = 0; k < W_; k++) acc += s_r[k] * __ldg(Wf + (H_ + k) * H_ + tid);
    y[b * H_ + tid] = acc;
}

// ---------------------------------------------------------------------------
extern "C" void kernel_launch(void* const* d_in, const int* in_sizes, int n_in,
                              void* d_out, int out_size) {
    const float* inputs = (const float*)d_in[0];
    const float* h_prev = (const float*)d_in[1];
    const float* c_prev = (const float*)d_in[2];
    const float* M_prev = (const float*)d_in[3];
    const float* wr_prev = (const float*)d_in[4];
    const float* usage_prev = (const float*)d_in[5];
    const float* r_prev = (const float*)d_in[6];
    const float* Wk = (const float*)d_in[7];
    const float* Uk = (const float*)d_in[8];
    const float* b_lstm = (const float*)d_in[9];
    const float* Wp = (const float*)d_in[10];
    const float* bp = (const float*)d_in[11];
    const float* Wf = (const float*)d_in[12];
    const float* bf = (const float*)d_in[13];

    float* out = (float*)d_out;
    float* o_y  = out + OFF_Y;
    float* o_h  = out + OFF_H;
    float* o_c  = out + OFF_C;
    float* o_M  = out + OFF_M;
    float* o_wr = out + OFF_WR;
    float* o_us = out + OFF_US;
    float* o_r  = out + OFF_R;

    k_gemm_z<<<512, 256>>>(inputs, r_prev, h_prev, Wk, Uk);
    k_hparams<<<64, 256>>>(c_prev, b_lstm, Wp, bp, o_h, o_c);
    k_fused<<<8192, 256>>>(M_prev, wr_prev, usage_prev, o_M, o_wr, o_us);
    k_sel<<<1024, 256>>>(usage_prev);
    k_final<<<64, 512>>>(M_prev, wr_prev, o_h, Wf, bf, o_M, o_wr, o_us, o_r, o_y);
}

// round 8
// speedup vs baseline: 1.2453x; 1.0269x over previous
#include <cuda_runtime.h>
#include <cuda_bf16.h>
#include <cstdint>
#include <cfloat>

#define B_    64
#define H_    512
#define N_    16384
#define W_    64
#define DIN_  512
#define KDIM_ 1088
#define G4_   2048
#define KSPLIT_ 8
#define KPER_   136   // 1088/8

// d_out layout (floats)
#define OFF_Y   0
#define OFF_H   32768
#define OFF_C   65536
#define OFF_M   98304
#define OFF_WR  67207168
#define OFF_US  68255744
#define OFF_R   69304320

typedef unsigned long long u64;

// scratch
__device__ float g_zp[KSPLIT_ * B_ * G4_];
__device__ float g_qn[B_ * W_];
__device__ float g_a[B_ * W_];
__device__ float g_e[B_ * W_];
__device__ float g_alpha[B_];
__device__ float g_gamma[B_];
__device__ float g_sim[B_ * N_];

__device__ __forceinline__ float sigmoidf_(float x) { return 1.0f / (1.0f + expf(-x)); }

// ---- packed-key top-k primitives (constant-index CE networks only) ----
__device__ __forceinline__ u64 umax64(u64 a, u64 b) { return a > b ? a : b; }
__device__ __forceinline__ u64 umin64(u64 a, u64 b) { return a < b ? a : b; }
#define CE_DESC(x, y) { u64 _mx = umax64(x, y); u64 _mn = umin64(x, y); (x) = _mx; (y) = _mn; }

__device__ __forceinline__ u64 pack_key(float v, int n) {
    unsigned vb = __float_as_uint(v);
    vb = (vb & 0x80000000u) ? ~vb : (vb | 0x80000000u);
    return ((u64)vb << 32) | (unsigned)(0xFFFFFFFFu - (unsigned)n);
}
__device__ __forceinline__ float key_val(u64 k) {
    unsigned vb = (unsigned)(k >> 32);
    vb = (vb & 0x80000000u) ? (vb ^ 0x80000000u) : ~vb;
    return __uint_as_float(vb);
}
__device__ __forceinline__ int key_idx(u64 k) {
    return (int)(0xFFFFFFFFu - (unsigned)(k & 0xFFFFFFFFull));
}

__device__ __forceinline__ void insert4(u64* a, u64 x) {
    if (x > a[3]) {
        a[3] = x;
        if (a[3] > a[2]) { u64 t = a[2]; a[2] = a[3]; a[3] = t; }
        if (a[2] > a[1]) { u64 t = a[1]; a[1] = a[2]; a[2] = t; }
        if (a[1] > a[0]) { u64 t = a[0]; a[0] = a[1]; a[1] = t; }
    }
}

__device__ __forceinline__ void insert5(u64* a, u64 x) {
    if (x > a[4]) {
        a[4] = x;
        if (a[4] > a[3]) { u64 t = a[3]; a[3] = a[4]; a[4] = t; }
        if (a[3] > a[2]) { u64 t = a[2]; a[2] = a[3]; a[3] = t; }
        if (a[2] > a[1]) { u64 t = a[1]; a[1] = a[2]; a[2] = t; }
        if (a[1] > a[0]) { u64 t = a[0]; a[0] = a[1]; a[1] = t; }
    }
}

// top-4 merge: a sorted desc merged with brev (other list reversed)
__device__ __forceinline__ void bmerge4(u64* a, const u64* brev) {
    a[0] = umax64(a[0], brev[0]); a[1] = umax64(a[1], brev[1]);
    a[2] = umax64(a[2], brev[2]); a[3] = umax64(a[3], brev[3]);
    CE_DESC(a[0], a[2]); CE_DESC(a[1], a[3]);
    CE_DESC(a[0], a[1]); CE_DESC(a[2], a[3]);
}

// top-5 merge: elementwise max vs reversed, then 10-CE insertion network
__device__ __forceinline__ void bmerge5(u64* a, const u64* brev) {
#pragma unroll
    for (int j = 0; j < 5; j++) a[j] = umax64(a[j], brev[j]);
#pragma unroll
    for (int i = 1; i < 5; i++)
#pragma unroll
        for (int j = i; j > 0; j--)
            CE_DESC(a[j-1], a[j]);
}

template<int MAXOFF>
__device__ __forceinline__ void warp_bmerge4(u64* a) {
#pragma unroll
    for (int off = MAXOFF; off > 0; off >>= 1) {
        u64 b[4];
#pragma unroll
        for (int j = 0; j < 4; j++) b[j] = __shfl_down_sync(0xffffffffu, a[3-j], off);
        bmerge4(a, b);
    }
}

template<int MAXOFF>
__device__ __forceinline__ void warp_bmerge5(u64* a) {
#pragma unroll
    for (int off = MAXOFF; off > 0; off >>= 1) {
        u64 b[5];
#pragma unroll
        for (int j = 0; j < 5; j++) b[j] = __shfl_down_sync(0xffffffffu, a[4-j], off);
        bmerge5(a, b);
    }
}

// ---------------------------------------------------------------------------
// K1: z partials. grid = 32 j-tiles x 8 k-splits = 256 blocks, 256 threads.
// ---------------------------------------------------------------------------
__global__ void k_gemm_z(const float* __restrict__ inp, const float* __restrict__ rprev,
                         const float* __restrict__ hprev, const float* __restrict__ Wk,
                         const float* __restrict__ Uk) {
    __shared__ __align__(16) float Xs[8][64];
    __shared__ __align__(16) float Ws[8][64];
    const int jt = blockIdx.x & 31;
    const int ks = blockIdx.x >> 5;
    const int j0 = jt * 64;
    const int kbase = ks * KPER_;
    const int t = threadIdx.x;
    const int tj = t & 15;
    const int tb = t >> 4;

    float acc[4][4];
#pragma unroll
    for (int r = 0; r < 4; r++)
#pragma unroll
        for (int c = 0; c < 4; c++) acc[r][c] = 0.0f;

    for (int cch = 0; cch < 17; cch++) {
        const int k0 = kbase + cch * 8;
        for (int idx = t; idx < 512; idx += 256) {
            int b = idx >> 3, kk = idx & 7, kg = k0 + kk;
            float v;
            if (kg < DIN_)            v = inp[b * DIN_ + kg];
            else if (kg < DIN_ + W_)  v = rprev[b * W_ + (kg - DIN_)];
            else                      v = hprev[b * H_ + (kg - DIN_ - W_)];
            Xs[kk][b] = v;
        }
        for (int idx = t; idx < 512; idx += 256) {
            int kk = idx >> 6, jj = idx & 63, kg = k0 + kk;
            float w = (kg < DIN_ + W_) ? Wk[kg * G4_ + j0 + jj]
                                       : Uk[(kg - DIN_ - W_) * G4_ + j0 + jj];
            Ws[kk][jj] = w;
        }
        __syncthreads();
#pragma unroll
        for (int kk = 0; kk < 8; kk++) {
            float4 xv = *(const float4*)&Xs[kk][tb * 4];
            float4 wv = *(const float4*)&Ws[kk][tj * 4];
            float xr[4] = {xv.x, xv.y, xv.z, xv.w};
            float wc[4] = {wv.x, wv.y, wv.z, wv.w};
#pragma unroll
            for (int r = 0; r < 4; r++)
#pragma unroll
                for (int c = 0; c < 4; c++) acc[r][c] += xr[r] * wc[c];
        }
        __syncthreads();
    }
#pragma unroll
    for (int r = 0; r < 4; r++) {
        float4 st = make_float4(acc[r][0], acc[r][1], acc[r][2], acc[r][3]);
        *(float4*)&g_zp[ks * (B_ * G4_) + (tb * 4 + r) * G4_ + j0 + tj * 4] = st;
    }
}

// ---------------------------------------------------------------------------
// K2: z reduce + gates + params + derive. grid=64 (b), block=512
// ---------------------------------------------------------------------------
__global__ void k_hparams(const float* __restrict__ cprev, const float* __restrict__ bl,
                          const float* __restrict__ Wp, const float* __restrict__ bp,
                          float* __restrict__ h_out, float* __restrict__ c_out) {
    __shared__ float zz[G4_];
    __shared__ float sh[H_];
    __shared__ float sp[194];
    __shared__ float ws[2];
    const int b = blockIdx.x, tid = threadIdx.x;

#pragma unroll
    for (int i = 0; i < 4; i++) {
        const int hh = tid + i * 512;
        float z = bl[hh];
#pragma unroll
        for (int ks = 0; ks < KSPLIT_; ks++)
            z += g_zp[ks * (B_ * G4_) + b * G4_ + hh];
        zz[hh] = z;
    }
    __syncthreads();

    {
        const int hh = tid;
        float ig = sigmoidf_(zz[hh]);
        float fg = sigmoidf_(zz[H_ + hh]);
        float og = sigmoidf_(zz[3 * H_ + hh]);
        float c  = fg * cprev[b * H_ + hh] + ig * tanhf(zz[2 * H_ + hh]);
        float h  = og * tanhf(c);
        c_out[b * H_ + hh] = c;
        h_out[b * H_ + hh] = h;
        sh[hh] = h;
    }
    __syncthreads();

    if (tid < 194) {
        float acc = bp[tid];
#pragma unroll 8
        for (int k = 0; k < H_; k++) acc += sh[k] * Wp[k * 194 + tid];
        sp[tid] = acc;
    }
    __syncthreads();

    if (tid < 64) {
        float q = sp[tid];
        float s = q * q;
#pragma unroll
        for (int off = 16; off > 0; off >>= 1) s += __shfl_down_sync(0xffffffffu, s, off);
        if ((tid & 31) == 0) ws[tid >> 5] = s;
    }
    __syncthreads();
    if (tid < 64) {
        float tot = ws[0] + ws[1];
        g_qn[b * W_ + tid] = sp[tid] * rsqrtf(fmaxf(tot, 1e-12f));
        g_a[b * W_ + tid]  = sp[W_ + tid];
        g_e[b * W_ + tid]  = sigmoidf_(sp[2 * W_ + tid]);
        if (tid == 0) {
            g_alpha[b] = sigmoidf_(sp[192]);
            g_gamma[b] = sigmoidf_(sp[193]);
        }
    }
}

// ---------------------------------------------------------------------------
// K3 (FUSED): one pass over M: sim + base M update + us/wr streams.
// grid = 8192 blocks (128 rows each), block = 256.
// ---------------------------------------------------------------------------
__global__ void k_fused(const float* __restrict__ M, const float* __restrict__ wrp,
                        const float* __restrict__ usprev,
                        float* __restrict__ Mout, float* __restrict__ wr_out,
                        float* __restrict__ us_out) {
    const int b  = blockIdx.x >> 7;
    const int n0 = (blockIdx.x & 127) << 7;
    const int tid = threadIdx.x;
    __shared__ __align__(16) float se[W_], sa[W_], sq[W_];
    __shared__ float s_sim[128];
    __shared__ float s_ag;
    if (tid < W_) { se[tid] = g_e[b * W_ + tid]; sa[tid] = g_a[b * W_ + tid]; sq[tid] = g_qn[b * W_ + tid]; }
    if (tid == 0) s_ag = g_alpha[b] * g_gamma[b];
    __syncthreads();

    const int lane = tid & 31, warp = tid >> 5;
    const int half = lane >> 4, l16 = lane & 15;
    const int rbase = warp * 2 + half;
    const size_t browoff = (size_t)b * N_ + n0;

    float4 m[8];
    float wr[8];
#pragma unroll
    for (int i = 0; i < 8; i++)
        m[i] = __ldcs((const float4*)(M + (browoff + i * 16 + rbase) * W_) + l16);
#pragma unroll
    for (int i = 0; i < 8; i++)
        wr[i] = __ldg(wrp + browoff + i * 16 + rbase);

    if (tid < 32) {
        float4 up = __ldcs((const float4*)(usprev + browoff) + tid);
        __stcs((float4*)(us_out + browoff) + tid,
               make_float4(up.x + 1.0f, up.y + 1.0f, up.z + 1.0f, up.w + 1.0f));
        __stcs((float4*)(wr_out + browoff) + tid, make_float4(0.f, 0.f, 0.f, 0.f));
    }

    const float4 e4 = *(const float4*)(se + l16 * 4);
    const float4 a4 = *(const float4*)(sa + l16 * 4);
    const float4 q4 = *(const float4*)(sq + l16 * 4);
    const float ag = s_ag;

#pragma unroll
    for (int i = 0; i < 8; i++) {
        float dot = m[i].x * q4.x + m[i].y * q4.y + m[i].z * q4.z + m[i].w * q4.w;
        float ss  = m[i].x * m[i].x + m[i].y * m[i].y + m[i].z * m[i].z + m[i].w * m[i].w;
#pragma unroll
        for (int off = 8; off > 0; off >>= 1) {
            dot += __shfl_down_sync(0xffffffffu, dot, off);
            ss  += __shfl_down_sync(0xffffffffu, ss,  off);
        }
        if (l16 == 0) s_sim[i * 16 + rbase] = dot * rsqrtf(fmaxf(ss, 1e-12f));

        const float ww = ag * wr[i];
        float4 o;
        o.x = m[i].x * (1.0f - ww * e4.x) + ww * a4.x;
        o.y = m[i].y * (1.0f - ww * e4.y) + ww * a4.y;
        o.z = m[i].z * (1.0f - ww * e4.z) + ww * a4.z;
        o.w = m[i].w * (1.0f - ww * e4.w) + ww * a4.w;
        __stcs((float4*)(Mout + (browoff + i * 16 + rbase) * W_) + l16, o);
    }
    __syncthreads();
    if (tid < 128) g_sim[browoff + tid] = s_sim[tid];
}

// ---------------------------------------------------------------------------
// K4 (FINAL): per-b everything. grid=64, block=1024.
// sim half (tid<512): top-4 of sim; usage half: top-5 of usage_prev.
// Then softmax, lru, r_curr, lru-row fix, wr/us fixups, y_out.
// ---------------------------------------------------------------------------
__global__ void __launch_bounds__(1024)
k_final(const float* __restrict__ Mprev, const float* __restrict__ wrp,
        const float* __restrict__ usprev,
        const float* __restrict__ h, const float* __restrict__ Wf,
        const float* __restrict__ bf,
        float* __restrict__ Mout, float* __restrict__ wr_out,
        float* __restrict__ us_out, float* __restrict__ r_out,
        float* __restrict__ y) {
    const int b = blockIdx.x, tid = threadIdx.x;
    const int lane = tid & 31, warp = tid >> 5;
    __shared__ float xs[H_];
    __shared__ float s_r[W_];
    __shared__ float s_p[4];
    __shared__ int   s_idx[4];
    __shared__ u64   s_uk[5];
    __shared__ int   s_lru;
    __shared__ u64   swv[16][4];   // sim warp candidates
    __shared__ u64   suv[16][5];   // usage warp candidates

    if (tid < H_) xs[tid] = h[b * H_ + tid];

    if (tid < 512) {
        // ---- sim top-4 ----
        const float4* simb = (const float4*)(g_sim + b * N_);
        u64 a[4] = {0ull, 0ull, 0ull, 0ull};
#pragma unroll
        for (int i = 0; i < 8; i++) {
            const int f4 = tid + i * 512;
            float4 v = simb[f4];
            const int nb = f4 * 4;
            insert4(a, pack_key(v.x, nb + 0));
            insert4(a, pack_key(v.y, nb + 1));
            insert4(a, pack_key(v.z, nb + 2));
            insert4(a, pack_key(v.w, nb + 3));
        }
        warp_bmerge4<16>(a);
        if (lane == 0) {
#pragma unroll
            for (int j = 0; j < 4; j++) swv[warp][j] = a[j];
        }
    } else {
        // ---- usage top-5 ----
        const int t = tid - 512;
        const float4* usb = (const float4*)(usprev + b * N_);
        u64 a[5] = {0ull, 0ull, 0ull, 0ull, 0ull};
#pragma unroll
        for (int i = 0; i < 8; i++) {
            const int f4 = t + i * 512;
            float4 v = __ldcs(usb + f4);
            const int nb = f4 * 4;
            insert5(a, pack_key(v.x, nb + 0));
            insert5(a, pack_key(v.y, nb + 1));
            insert5(a, pack_key(v.z, nb + 2));
            insert5(a, pack_key(v.w, nb + 3));
        }
        warp_bmerge5<16>(a);
        if (lane == 0) {
#pragma unroll
            for (int j = 0; j < 5; j++) suv[warp - 16][j] = a[j];
        }
    }
    __syncthreads();

    if (warp == 0) {
        u64 a[4];
        if (lane < 16) {
#pragma unroll
            for (int j = 0; j < 4; j++) a[j] = swv[lane][j];
        } else {
#pragma unroll
            for (int j = 0; j < 4; j++) a[j] = 0ull;
        }
        warp_bmerge4<8>(a);
        if (lane == 0) {
            float lv[4];
#pragma unroll
            for (int j = 0; j < 4; j++) lv[j] = key_val(a[j]);
            float vmax = lv[0], sum = 0.0f, ev[4];
#pragma unroll
            for (int j = 0; j < 4; j++) { ev[j] = expf(lv[j] - vmax); sum += ev[j]; }
            float inv = 1.0f / sum;
#pragma unroll
            for (int j = 0; j < 4; j++) { s_p[j] = ev[j] * inv; s_idx[j] = key_idx(a[j]); }
        }
    } else if (warp == 16) {
        u64 a[5];
        if (lane < 16) {
#pragma unroll
            for (int j = 0; j < 5; j++) a[j] = suv[lane][j];
        } else {
#pragma unroll
            for (int j = 0; j < 5; j++) a[j] = 0ull;
        }
        warp_bmerge5<8>(a);
        if (lane == 0) {
#pragma unroll
            for (int j = 0; j < 5; j++) s_uk[j] = a[j];
        }
    }
    __syncthreads();

    if (tid == 0) {
        int lru = key_idx(s_uk[0]);
#pragma unroll
        for (int j = 0; j < 5; j++) {
            int c = key_idx(s_uk[j]);
            if (c != s_idx[0] && c != s_idx[1] && c != s_idx[2] && c != s_idx[3]) { lru = c; break; }
        }
        s_lru = lru;
    }
    if (tid >= 128 && tid < 192) {
        const int w = tid - 128;
        float r = s_p[0] * Mprev[((size_t)b * N_ + s_idx[0]) * W_ + w]
                + s_p[1] * Mprev[((size_t)b * N_ + s_idx[1]) * W_ + w]
                + s_p[2] * Mprev[((size_t)b * N_ + s_idx[2]) * W_ + w]
                + s_p[3] * Mprev[((size_t)b * N_ + s_idx[3]) * W_ + w];
        s_r[w] = r;
        r_out[b * W_ + w] = r;
    }
    if (tid >= 224 && tid < 228) {
        const int j = tid - 224;
        const int idx = s_idx[j];
        wr_out[b * N_ + idx] = s_p[j];
        us_out[b * N_ + idx] = 0.0f;
    }
    __syncthreads();

    if (tid >= 544 && tid < 560) {
        const int k = tid - 544;
        const int lru = s_lru;
        const float alpha = g_alpha[b], gamma = g_gamma[b];
        const float ww = alpha * (gamma * wrp[b * N_ + lru] + (1.0f - gamma));
        const size_t rowoff = ((size_t)b * N_ + lru) * W_;
        float4 mrow = *(const float4*)(Mprev + rowoff + k * 4);
        float4 e4 = *(const float4*)(g_e + b * W_ + k * 4);
        float4 a4 = *(const float4*)(g_a + b * W_ + k * 4);
        float4 o;
        o.x = mrow.x * (1.0f - ww * e4.x) + ww * a4.x;
        o.y = mrow.y * (1.0f - ww * e4.y) + ww * a4.y;
        o.z = mrow.z * (1.0f - ww * e4.z) + ww * a4.z;
        o.w = mrow.w * (1.0f - ww * e4.w) + ww * a4.w;
        *(float4*)(Mout + rowoff + k * 4) = o;
    }

    if (tid < H_) {
        float acc = bf[tid];
#pragma unroll 8
        for (int k = 0; k < H_; k++) acc += xs[k] * __ldg(Wf + k * H_ + tid);
#pragma unroll 8
        for (int k = 0; k < W_; k++) acc += s_r[k] * __ldg(Wf + (H_ + k) * H_ + tid);
        y[b * H_ + tid] = acc;
    }
}

// ---------------------------------------------------------------------------
extern "C" void kernel_launch(void* const* d_in, const int* in_sizes, int n_in,
                              void* d_out, int out_size) {
    const float* inputs = (const float*)d_in[0];
    const float* h_prev = (const float*)d_in[1];
    const float* c_prev = (const float*)d_in[2];
    const float* M_prev = (const float*)d_in[3];
    const float* wr_prev = (const float*)d_in[4];
    const float* usage_prev = (const float*)d_in[5];
    const float* r_prev = (const float*)d_in[6];
    const float* Wk = (const float*)d_in[7];
    const float* Uk = (const float*)d_in[8];
    const float* b_lstm = (const float*)d_in[9];
    const float* Wp = (const float*)d_in[10];
    const float* bp = (const float*)d_in[11];
    const float* Wf = (const float*)d_in[12];
    const float* bf = (const float*)d_in[13];

    float* out = (float*)d_out;
    float* o_y  = out + OFF_Y;
    float* o_h  = out + OFF_H;
    float* o_c  = out + OFF_C;
    float* o_M  = out + OFF_M;
    float* o_wr = out + OFF_WR;
    float* o_us = out + OFF_US;
    float* o_r  = out + OFF_R;

    k_gemm_z<<<256, 256>>>(inputs, r_prev, h_prev, Wk, Uk);
    k_hparams<<<64, 512>>>(c_prev, b_lstm, Wp, bp, o_h, o_c);
    k_fused<<<8192, 256>>>(M_prev, wr_prev, usage_prev, o_M, o_wr, o_us);
    k_final<<<64, 1024>>>(M_prev, wr_prev, usage_prev, o_h, Wf, bf,
                          o_M, o_wr, o_us, o_r, o_y);
}